// round 16
// baseline (speedup 1.0000x reference)
#include <cuda_runtime.h>
#include <cuda_bf16.h>
#include <cuda_fp16.h>
#include <math.h>
#include <cstdint>

#define BB 2
#define SS 2048
#define EE 1024
#define HH 16
#define HD 64
#define BH (BB*HH)
#define SCALE_L2E 0.18033688f   // 0.125 * log2(e); attention uses exp2

// Scratch (16B-aligned)
static __device__ __align__(16) uint32_t g_qb[(size_t)BH*SS*32];      // Q fp16x2, scaled
static __device__ __align__(16) uint32_t g_kb[(size_t)BH*SS*32];      // K fp16x2
static __device__ __align__(16) uint32_t g_vb[(size_t)BH*64*(SS/2)];  // V fp16x2, v-major
static __device__ __align__(16) uint32_t g_at[(size_t)BB*SS*(EE/2)];  // att fp16x2, A-frag layout
static __device__ __align__(16) uint32_t g_wo[(size_t)EE*(EE/2)];     // Wo^T fp16x2, B-frag layout

__device__ __forceinline__ uint32_t pack_h2(float a, float b) {
    __half2 h = __floats2half2_rn(a, b);
    return *reinterpret_cast<uint32_t*>(&h);
}
__device__ __forceinline__ uint32_t cvt2_h2(float lo, float hi) {
    uint32_t r; asm("cvt.rn.f16x2.f32 %0, %1, %2;" : "=r"(r) : "f"(hi), "f"(lo)); return r;
}
__device__ __forceinline__ uint32_t ex2_h2(uint32_t x) {
    uint32_t r; asm("ex2.approx.f16x2 %0, %1;" : "=r"(r) : "r"(x)); return r;
}
__device__ __forceinline__ float2 h22f2(uint32_t h) {
    __half2 hh = *reinterpret_cast<__half2*>(&h);
    return __half22float2(hh);
}
__device__ __forceinline__ uint32_t smem_u32(const void* p) {
    uint32_t a;
    asm("{ .reg .u64 t; cvta.to.shared.u64 t, %1; cvt.u32.u64 %0, t; }" : "=r"(a) : "l"(p));
    return a;
}
#define CPA16(d, s) asm volatile("cp.async.ca.shared.global [%0], [%1], 16;" :: "r"(d), "l"(s) : "memory")
#define CPC()       asm volatile("cp.async.commit_group;" ::: "memory")
#define CPW(n)      asm volatile("cp.async.wait_group %0;" :: "n"(n) : "memory")

__device__ __forceinline__ void mma_f16(float c[4], uint32_t a0, uint32_t a1, uint32_t a2,
                                        uint32_t a3, uint32_t b0, uint32_t b1) {
    asm volatile("mma.sync.aligned.m16n8k16.row.col.f32.f16.f16.f32 "
        "{%0,%1,%2,%3}, {%4,%5,%6,%7}, {%8,%9}, {%0,%1,%2,%3};"
        : "+f"(c[0]), "+f"(c[1]), "+f"(c[2]), "+f"(c[3])
        : "r"(a0), "r"(a1), "r"(a2), "r"(a3), "r"(b0), "r"(b1));
}

// ---------------------------------------------------------------------------
// Kernel 1 (fused): blocks [0,512) = QKV projection (fp16 mma);
//                   blocks [512,768) = Wo pack (fp16, B-frag layout).
// (unchanged from R15 passing version)
// ---------------------------------------------------------------------------
#define QKV_SMEM_BYTES 41984

__global__ __launch_bounds__(256, 3) void qkv_wo_kernel(
    const float* __restrict__ x,
    const float* __restrict__ Wq, const float* __restrict__ bq,
    const float* __restrict__ Wk, const float* __restrict__ bk,
    const float* __restrict__ Wv, const float* __restrict__ bv,
    const float* __restrict__ Wo)
{
    extern __shared__ __align__(16) uint32_t smq[];
    int tid = threadIdx.x;
    int blk = blockIdx.x;

    if (blk >= 512) {   // ---- Wo pack ----
        float (*t)[65] = (float(*)[65])smq;
        int wid = blk - 512;
        int k0 = (wid & 15)*64, n0 = (wid >> 4)*64;
        for (int idx = tid; idx < 4096; idx += 256) {
            int ki = idx >> 6, n = idx & 63;
            t[ki][n] = Wo[(size_t)(k0 + ki)*EE + n0 + n];
        }
        __syncthreads();
        int nl = tid >> 2, qq = tid & 3;
        uint32_t hv[8];
        #pragma unroll
        for (int j = 0; j < 8; ++j) {
            int pr = 4*j + qq;
            hv[j] = pack_h2(t[2*pr][nl], t[2*pr + 1][nl]);
        }
        size_t ob = (size_t)(n0 + nl)*(EE/2) + (k0 >> 6)*32 + qq*8;
        *(uint4*)&g_wo[ob]     = make_uint4(hv[0], hv[1], hv[2], hv[3]);
        *(uint4*)&g_wo[ob + 4] = make_uint4(hv[4], hv[5], hv[6], hv[7]);
        return;
    }

    // ---- QKV (fp16 mma) ----
    uint32_t* At16 = smq;                     // [128 m][32 pos], XOR-swizzled
    float*    Wsf  = (float*)(smq + 4096);    // [64 k][n] stride 68
    uint32_t* Bs   = smq + 8448;              // [64 n][32 pos], XOR-swizzled
    float*    Vt   = (float*)smq;             // overlay

    int lane = tid & 31, warp = tid >> 5;
    int g = lane >> 2, q = lane & 3;
    int bh = blk & 31, b = bh >> 4, h = bh & 15;
    int s0 = (blk >> 5) * 128, wm = warp * 16;

    for (int idx = tid; idx < 2048; idx += 256) {
        int row = idx >> 4, i = idx & 15;
        float4 v = *(const float4*)&x[((size_t)b*SS + s0 + row)*EE + h*HD + i*4];
        int p0 = ((2*i) & 3)*8 + (i >> 1);
        int p1 = ((2*i + 1) & 3)*8 + (i >> 1);
        int sw0 = ((p0 >> 2) ^ (row & 7))*4 + (p0 & 3);
        int sw1 = ((p1 >> 2) ^ (row & 7))*4 + (p1 & 3);
        At16[row*32 + sw0] = pack_h2(v.x, v.y);
        At16[row*32 + sw1] = pack_h2(v.z, v.w);
    }
    __syncthreads();

    int u0c = ((2*q) ^ g)*4;
    int u1c = ((2*q + 1) ^ g)*4;
    uint32_t qa[8], qg[8];
    {
        int ra0 = (wm + g)*32, ra1 = (wm + g + 8)*32;
        uint4 a0 = *(const uint4*)&At16[ra0 + u0c], a1 = *(const uint4*)&At16[ra0 + u1c];
        uint4 c0 = *(const uint4*)&At16[ra1 + u0c], c1 = *(const uint4*)&At16[ra1 + u1c];
        qa[0]=a0.x; qa[1]=a0.y; qa[2]=a0.z; qa[3]=a0.w; qa[4]=a1.x; qa[5]=a1.y; qa[6]=a1.z; qa[7]=a1.w;
        qg[0]=c0.x; qg[1]=c0.y; qg[2]=c0.z; qg[3]=c0.w; qg[4]=c1.x; qg[5]=c1.y; qg[6]=c1.z; qg[7]=c1.w;
    }

    int r0g = s0 + wm + g, r1g = s0 + wm + g + 8;
    const float* Wp[3] = {Wq, Wk, Wv};
    const float* bp[3] = {bq, bk, bv};

    for (int w = 0; w < 3; ++w) {
        for (int idx = tid; idx < 1024; idx += 256) {
            int row = idx >> 4, c4 = (idx & 15)*4;
            *(float4*)&Wsf[row*68 + c4] = *(const float4*)&Wp[w][(size_t)row*64 + c4];
        }
        __syncthreads();
        {
            int n = tid >> 2, qq = tid & 3;
            #pragma unroll
            for (int j = 0; j < 8; ++j) {
                int c = 8*j + 2*qq;
                int p = qq*8 + j;
                int sw = ((p >> 2) ^ (n & 7))*4 + (p & 3);
                Bs[n*32 + sw] = pack_h2(Wsf[c*68 + n], Wsf[(c + 1)*68 + n]);
            }
        }
        __syncthreads();

        float acc[8][4] = {};
        #pragma unroll
        for (int nb = 0; nb < 8; ++nb) {
            int rb = (8*nb + g)*32;
            uint4 b0 = *(const uint4*)&Bs[rb + u0c];
            uint4 b1 = *(const uint4*)&Bs[rb + u1c];
            mma_f16(acc[nb], qa[0], qg[0], qa[1], qg[1], b0.x, b0.y);
            mma_f16(acc[nb], qa[2], qg[2], qa[3], qg[3], b0.z, b0.w);
            mma_f16(acc[nb], qa[4], qg[4], qa[5], qg[5], b1.x, b1.y);
            mma_f16(acc[nb], qa[6], qg[6], qa[7], qg[7], b1.z, b1.w);
        }

        if (w == 0) {
            #pragma unroll
            for (int nb = 0; nb < 8; ++nb) {
                int c = nb*8 + 2*q;
                float b0 = bp[0][c], b1 = bp[0][c+1];
                g_qb[((size_t)bh*SS + r0g)*32 + q*8 + nb] = pack_h2((acc[nb][0]+b0)*SCALE_L2E, (acc[nb][1]+b1)*SCALE_L2E);
                g_qb[((size_t)bh*SS + r1g)*32 + q*8 + nb] = pack_h2((acc[nb][2]+b0)*SCALE_L2E, (acc[nb][3]+b1)*SCALE_L2E);
            }
            __syncthreads();
        } else if (w == 1) {
            #pragma unroll
            for (int nb = 0; nb < 8; ++nb) {
                int c = nb*8 + 2*q;
                float b0 = bp[1][c], b1 = bp[1][c+1];
                g_kb[((size_t)bh*SS + r0g)*32 + q*8 + nb] = pack_h2(acc[nb][0]+b0, acc[nb][1]+b1);
                g_kb[((size_t)bh*SS + r1g)*32 + q*8 + nb] = pack_h2(acc[nb][2]+b0, acc[nb][3]+b1);
            }
            __syncthreads();
        } else {
            __syncthreads();
            int rl0 = wm + g, rl1 = wm + g + 8;
            #pragma unroll
            for (int nb = 0; nb < 8; ++nb) {
                int c = nb*8 + 2*q;
                float b0 = bp[2][c], b1 = bp[2][c+1];
                Vt[rl0*65 + c] = acc[nb][0]+b0; Vt[rl0*65 + c+1] = acc[nb][1]+b1;
                Vt[rl1*65 + c] = acc[nb][2]+b0; Vt[rl1*65 + c+1] = acc[nb][3]+b1;
            }
            __syncthreads();
            int v = tid & 63, idx2 = tid >> 6, tl = idx2 >> 1, half = idx2 & 1;
            uint32_t hv[16];
            #pragma unroll
            for (int j = 0; j < 16; ++j) {
                int pos = half*16 + j;
                int qv = pos >> 3, kk = (pos & 7) >> 1, hh = pos & 1;
                int sl = tl*64 + 2*(8*kk + 4*hh + qv);
                hv[j] = pack_h2(Vt[sl*65 + v], Vt[(sl+1)*65 + v]);
            }
            size_t ob = ((size_t)bh*64 + v)*(SS/2) + (s0 >> 1) + tl*32 + half*16;
            #pragma unroll
            for (int u = 0; u < 4; ++u)
                *(uint4*)&g_vb[ob + 4*u] = make_uint4(hv[4*u], hv[4*u+1], hv[4*u+2], hv[4*u+3]);
        }
    }
}

// ---------------------------------------------------------------------------
// Kernel 2: attention, fp16 mma, 128-row KV tiles (2x64 halves per stage),
// 2-stage cp.async pipeline: 16 iterations, one sync each.
// Stage (u32): K[0,4096) rows 0..127 stride 32 | V[4096,8192) 64 v-rows stride 64
// ---------------------------------------------------------------------------
#define SSTG (128*32 + 64*64)           // 8192 u32 = 32KB
#define ATTN_SMEM_BYTES (2*SSTG*4)      // 65536

__global__ __launch_bounds__(256, 2) void attn_kernel(const float* __restrict__ mask)
{
    extern __shared__ __align__(16) uint32_t smu[];
    uint32_t smb = smem_u32(smu);

    int tid = threadIdx.x, lane = tid & 31, warp = tid >> 5;
    int g = lane >> 2, q = lane & 3;
    int bh = blockIdx.x, b = bh >> 4, h = bh & 15;
    int q0 = blockIdx.y * 128, wr = q0 + warp*16;

    int r8 = tid >> 3, seg = tid & 7;
    int vr = tid >> 2, s4 = tid & 3;
    const char* srcK = (const char*)g_kb + ((size_t)bh*SS)*128;
    const char* srcV = (const char*)g_vb + ((size_t)bh*64)*(SS/2)*4;

    // prefetch macro-tile 0 into stage 0
    {
        uint32_t base = smb;
        #pragma unroll
        for (int t = 0; t < 4; ++t) {
            int row = r8 + 32*t;
            int sc = (seg ^ (row & 7))*16;
            CPA16(base + row*128 + seg*16, srcK + (size_t)row*128 + sc);
        }
        uint32_t vbase = base + 16384;
        #pragma unroll
        for (int t = 0; t < 4; ++t) {
            int seg16 = s4 + 4*t, half = seg16 >> 3, sg = seg16 & 7;
            int sc = half*128 + (sg ^ (vr & 7))*16;
            CPA16(vbase + vr*256 + seg16*16, srcV + ((size_t)vr*(SS/2))*4 + sc);
        }
        CPC();
    }

    uint32_t qa[8], qg[8];
    {
        const uint4* p0 = (const uint4*)&g_qb[((size_t)bh*SS + wr + g)*32 + q*8];
        const uint4* p1 = (const uint4*)&g_qb[((size_t)bh*SS + wr + g + 8)*32 + q*8];
        uint4 u0 = p0[0], u1 = p0[1], v0 = p1[0], v1 = p1[1];
        qa[0]=u0.x; qa[1]=u0.y; qa[2]=u0.z; qa[3]=u0.w; qa[4]=u1.x; qa[5]=u1.y; qa[6]=u1.z; qa[7]=u1.w;
        qg[0]=v0.x; qg[1]=v0.y; qg[2]=v0.z; qg[3]=v0.w; qg[4]=v1.x; qg[5]=v1.y; qg[6]=v1.z; qg[7]=v1.w;
    }

    float oacc[8][4] = {};
    float lsum0 = 0.f, lsum1 = 0.f;
    const float* mrow0 = &mask[(size_t)(wr + g)*SS];
    const float* mrow1 = &mask[(size_t)(wr + g + 8)*SS];
    int u0c = ((2*q) ^ g)*4;
    int u1c = ((2*q + 1) ^ g)*4;

    for (int it = 0; it < 16; ++it) {
        CPW(0);
        __syncthreads();
        if (it + 1 < 16) {
            int s0n = (it + 1)*128;
            uint32_t base = smb + ((it + 1) & 1)*SSTG*4;
            #pragma unroll
            for (int t = 0; t < 4; ++t) {
                int row = r8 + 32*t;
                int sc = (seg ^ (row & 7))*16;
                CPA16(base + row*128 + seg*16, srcK + (size_t)(s0n + row)*128 + sc);
            }
            uint32_t vbase = base + 16384;
            #pragma unroll
            for (int t = 0; t < 4; ++t) {
                int seg16 = s4 + 4*t, half = seg16 >> 3, sg = seg16 & 7;
                int sc = half*128 + (sg ^ (vr & 7))*16;
                CPA16(vbase + vr*256 + seg16*16, srcV + ((size_t)vr*(SS/2) + (s0n >> 1))*4 + sc);
            }
            CPC();
        }

        const uint32_t* Kb = smu + (it & 1)*SSTG;
        const uint32_t* Vs = Kb + 4096;

        #pragma unroll
        for (int hf = 0; hf < 2; ++hf) {
            int s0 = it*128 + hf*64;
            const uint32_t* Kh = Kb + hf*64*32;

            // S = Q K^T
            float sacc[8][4] = {};
            #pragma unroll
            for (int nb = 0; nb < 8; ++nb) {
                int rb = (8*nb + g)*32;
                uint4 k0 = *(const uint4*)&Kh[rb + u0c];
                uint4 k1 = *(const uint4*)&Kh[rb + u1c];
                mma_f16(sacc[nb], qa[0], qg[0], qa[1], qg[1], k0.x, k0.y);
                mma_f16(sacc[nb], qa[2], qg[2], qa[3], qg[3], k0.z, k0.w);
                mma_f16(sacc[nb], qa[4], qg[4], qa[5], qg[5], k1.x, k1.y);
                mma_f16(sacc[nb], qa[6], qg[6], qa[7], qg[7], k1.z, k1.w);
            }

            // P = exp2(S * mask)
            uint32_t ph[8], pg[8];
            float ps0 = 0.f, ps1 = 0.f;
            #pragma unroll
            for (int nb = 0; nb < 8; ++nb) {
                float2 m0 = __ldg((const float2*)&mrow0[s0 + 8*nb + 2*q]);
                float2 m1 = __ldg((const float2*)&mrow1[s0 + 8*nb + 2*q]);
                uint32_t x01 = cvt2_h2(sacc[nb][0]*m0.x, sacc[nb][1]*m0.y);
                uint32_t x23 = cvt2_h2(sacc[nb][2]*m1.x, sacc[nb][3]*m1.y);
                ph[nb] = ex2_h2(x01);
                pg[nb] = ex2_h2(x23);
                float2 f0 = h22f2(ph[nb]);
                float2 f1 = h22f2(pg[nb]);
                ps0 += f0.x + f0.y;
                ps1 += f1.x + f1.y;
            }
            ps0 += __shfl_xor_sync(0xffffffffu, ps0, 1);
            ps0 += __shfl_xor_sync(0xffffffffu, ps0, 2);
            ps1 += __shfl_xor_sync(0xffffffffu, ps1, 1);
            ps1 += __shfl_xor_sync(0xffffffffu, ps1, 2);
            lsum0 += ps0; lsum1 += ps1;

            // O += P V
            #pragma unroll
            for (int nb = 0; nb < 8; ++nb) {
                int rb = (8*nb + g)*64 + hf*32;
                uint4 v0 = *(const uint4*)&Vs[rb + u0c];
                uint4 v1 = *(const uint4*)&Vs[rb + u1c];
                mma_f16(oacc[nb], ph[0], pg[0], ph[1], pg[1], v0.x, v0.y);
                mma_f16(oacc[nb], ph[2], pg[2], ph[3], pg[3], v0.z, v0.w);
                mma_f16(oacc[nb], ph[4], pg[4], ph[5], pg[5], v1.x, v1.y);
                mma_f16(oacc[nb], ph[6], pg[6], ph[7], pg[7], v1.z, v1.w);
            }
        }
    }

    float inv0 = 1.f/lsum0, inv1 = 1.f/lsum1;
    size_t base0 = ((size_t)b*SS + wr + g)*(EE/2) + h*32;
    size_t base1 = ((size_t)b*SS + wr + g + 8)*(EE/2) + h*32;
    #pragma unroll
    for (int nb = 0; nb < 8; ++nb) {
        int pos = q*8 + nb;
        g_at[base0 + pos] = pack_h2(oacc[nb][0]*inv0, oacc[nb][1]*inv0);
        g_at[base1 + pos] = pack_h2(oacc[nb][2]*inv1, oacc[nb][3]*inv1);
    }
}

// ---------------------------------------------------------------------------
// Kernel 3: output projection, fp16, 128-k chunks (2x64 halves per stage),
// 2-stage cp.async: 8 iterations.
// Stage (u32): A[0,8192) 128 rows stride 64 | B[8192,12288) 64 rows stride 64
// ---------------------------------------------------------------------------
#define OSTG 12288
#define OUT_SMEM_BYTES (2*OSTG*4)       // 98304

__global__ __launch_bounds__(256, 2) void out_kernel(
    const float* __restrict__ bo, float* __restrict__ out)
{
    extern __shared__ __align__(16) uint32_t smo[];
    uint32_t smb = smem_u32(smo);

    int tid = threadIdx.x, lane = tid & 31, warp = tid >> 5;
    int g = lane >> 2, q = lane & 3;
    int e0 = blockIdx.x*64, r0 = blockIdx.y*128, wm = warp*16;

    int r8 = tid >> 3, seg = tid & 7;
    int vr = tid >> 2, s4 = tid & 3;
    const char* srcA = (const char*)g_at + (size_t)r0*(EE/2)*4;
    const char* srcB = (const char*)g_wo + (size_t)e0*(EE/2)*4;

    // prefetch chunk 0 into stage 0
    {
        uint32_t base = smb;
        #pragma unroll
        for (int t = 0; t < 4; ++t) {
            int row = r8 + 32*t;
            #pragma unroll
            for (int half = 0; half < 2; ++half) {
                int sc = half*128 + (seg ^ (row & 7))*16;
                CPA16(base + row*256 + half*128 + seg*16, srcA + ((size_t)row*(EE/2))*4 + sc);
            }
        }
        uint32_t bbase = base + 32768;
        #pragma unroll
        for (int t = 0; t < 4; ++t) {
            int seg16 = s4 + 4*t, half = seg16 >> 3, sg = seg16 & 7;
            int sc = half*128 + (sg ^ (vr & 7))*16;
            CPA16(bbase + vr*256 + seg16*16, srcB + ((size_t)vr*(EE/2))*4 + sc);
        }
        CPC();
    }

    int u0c = ((2*q) ^ g)*4;
    int u1c = ((2*q + 1) ^ g)*4;

    float oacc[8][4] = {};

    for (int j = 0; j < 8; ++j) {
        CPW(0);
        __syncthreads();
        if (j + 1 < 8) {
            int kc = (j + 1)*64;      // u32 offset of the 128-k chunk
            uint32_t base = smb + ((j + 1) & 1)*OSTG*4;
            #pragma unroll
            for (int t = 0; t < 4; ++t) {
                int row = r8 + 32*t;
                #pragma unroll
                for (int half = 0; half < 2; ++half) {
                    int sc = half*128 + (seg ^ (row & 7))*16;
                    CPA16(base + row*256 + half*128 + seg*16, srcA + ((size_t)row*(EE/2) + kc)*4 + sc);
                }
            }
            uint32_t bbase = base + 32768;
            #pragma unroll
            for (int t = 0; t < 4; ++t) {
                int seg16 = s4 + 4*t, half = seg16 >> 3, sg = seg16 & 7;
                int sc = half*128 + (sg ^ (vr & 7))*16;
                CPA16(bbase + vr*256 + seg16*16, srcB + ((size_t)vr*(EE/2) + kc)*4 + sc);
            }
            CPC();
        }

        const uint32_t* As = smo + (j & 1)*OSTG;
        const uint32_t* Bs = As + 8192;

        #pragma unroll
        for (int hf = 0; hf < 2; ++hf) {
            int ra0 = (wm + g)*64 + hf*32, ra1 = (wm + g + 8)*64 + hf*32;
            uint4 Aa0 = *(const uint4*)&As[ra0 + u0c], Aa1 = *(const uint4*)&As[ra0 + u1c];
            uint4 Ga0 = *(const uint4*)&As[ra1 + u0c], Ga1 = *(const uint4*)&As[ra1 + u1c];

            #pragma unroll
            for (int nb = 0; nb < 8; ++nb) {
                int rb = (8*nb + g)*64 + hf*32;
                uint4 b0 = *(const uint4*)&Bs[rb + u0c];
                uint4 b1 = *(const uint4*)&Bs[rb + u1c];
                mma_f16(oacc[nb], Aa0.x, Ga0.x, Aa0.y, Ga0.y, b0.x, b0.y);
                mma_f16(oacc[nb], Aa0.z, Ga0.z, Aa0.w, Ga0.w, b0.z, b0.w);
                mma_f16(oacc[nb], Aa1.x, Ga1.x, Aa1.y, Ga1.y, b1.x, b1.y);
                mma_f16(oacc[nb], Aa1.z, Ga1.z, Aa1.w, Ga1.w, b1.z, b1.w);
            }
        }
    }

    float* o0 = &out[(size_t)(r0 + wm + g)*EE + e0];
    float* o1 = &out[(size_t)(r0 + wm + g + 8)*EE + e0];
    #pragma unroll
    for (int nb = 0; nb < 8; ++nb) {
        int c = nb*8 + 2*q;
        float b0 = bo[e0 + c], b1 = bo[e0 + c + 1];
        o0[c] = oacc[nb][0] + b0; o0[c+1] = oacc[nb][1] + b1;
        o1[c] = oacc[nb][2] + b0; o1[c+1] = oacc[nb][3] + b1;
    }
}

// ---------------------------------------------------------------------------
extern "C" void kernel_launch(void* const* d_in, const int* in_sizes, int n_in,
                              void* d_out, int out_size)
{
    const float* x    = (const float*)d_in[0];
    const float* mask = (const float*)d_in[1];
    const float* Wq   = (const float*)d_in[2];
    const float* bq   = (const float*)d_in[3];
    const float* Wk   = (const float*)d_in[4];
    const float* bk   = (const float*)d_in[5];
    const float* Wv   = (const float*)d_in[6];
    const float* bv   = (const float*)d_in[7];
    const float* Wo   = (const float*)d_in[8];
    const float* bo   = (const float*)d_in[9];
    float* out = (float*)d_out;

    cudaFuncSetAttribute(qkv_wo_kernel, cudaFuncAttributeMaxDynamicSharedMemorySize, QKV_SMEM_BYTES);
    cudaFuncSetAttribute(attn_kernel,   cudaFuncAttributeMaxDynamicSharedMemorySize, ATTN_SMEM_BYTES);
    cudaFuncSetAttribute(out_kernel,    cudaFuncAttributeMaxDynamicSharedMemorySize, OUT_SMEM_BYTES);

    qkv_wo_kernel<<<768, 256, QKV_SMEM_BYTES>>>(x, Wq, bq, Wk, bk, Wv, bv, Wo);
    attn_kernel<<<dim3(BH, SS/128), 256, ATTN_SMEM_BYTES>>>(mask);
    out_kernel<<<dim3(EE/64, (BB*SS)/128), 256, OUT_SMEM_BYTES>>>(bo, out);
}

// round 17
// speedup vs baseline: 1.0333x; 1.0333x over previous
#include <cuda_runtime.h>
#include <cuda_bf16.h>
#include <cuda_fp16.h>
#include <math.h>
#include <cstdint>

#define BB 2
#define SS 2048
#define EE 1024
#define HH 16
#define HD 64
#define BH (BB*HH)
#define SCALE_L2E 0.18033688f   // 0.125 * log2(e); attention uses exp2

// Scratch (16B-aligned)
static __device__ __align__(16) uint32_t g_qb[(size_t)BH*SS*32];      // Q fp16x2, scaled
static __device__ __align__(16) uint32_t g_kb[(size_t)BH*SS*32];      // K fp16x2
static __device__ __align__(16) uint32_t g_vb[(size_t)BH*64*(SS/2)];  // V fp16x2, v-major
static __device__ __align__(16) uint32_t g_at[(size_t)BB*SS*(EE/2)];  // att fp16x2, A-frag layout
static __device__ __align__(16) uint32_t g_wo[(size_t)EE*(EE/2)];     // Wo^T fp16x2, B-frag layout

__device__ __forceinline__ uint32_t pack_h2(float a, float b) {
    __half2 h = __floats2half2_rn(a, b);
    return *reinterpret_cast<uint32_t*>(&h);
}
__device__ __forceinline__ uint32_t cvt2_h2(float lo, float hi) {
    uint32_t r; asm("cvt.rn.f16x2.f32 %0, %1, %2;" : "=r"(r) : "f"(hi), "f"(lo)); return r;
}
__device__ __forceinline__ uint32_t ex2_h2(uint32_t x) {
    uint32_t r; asm("ex2.approx.f16x2 %0, %1;" : "=r"(r) : "r"(x)); return r;
}
__device__ __forceinline__ float2 h22f2(uint32_t h) {
    __half2 hh = *reinterpret_cast<__half2*>(&h);
    return __half22float2(hh);
}
__device__ __forceinline__ uint32_t smem_u32(const void* p) {
    uint32_t a;
    asm("{ .reg .u64 t; cvta.to.shared.u64 t, %1; cvt.u32.u64 %0, t; }" : "=r"(a) : "l"(p));
    return a;
}
#define CPA16(d, s) asm volatile("cp.async.ca.shared.global [%0], [%1], 16;" :: "r"(d), "l"(s) : "memory")
#define CPC()       asm volatile("cp.async.commit_group;" ::: "memory")
#define CPW(n)      asm volatile("cp.async.wait_group %0;" :: "n"(n) : "memory")

__device__ __forceinline__ void mma_f16(float c[4], uint32_t a0, uint32_t a1, uint32_t a2,
                                        uint32_t a3, uint32_t b0, uint32_t b1) {
    asm volatile("mma.sync.aligned.m16n8k16.row.col.f32.f16.f16.f32 "
        "{%0,%1,%2,%3}, {%4,%5,%6,%7}, {%8,%9}, {%0,%1,%2,%3};"
        : "+f"(c[0]), "+f"(c[1]), "+f"(c[2]), "+f"(c[3])
        : "r"(a0), "r"(a1), "r"(a2), "r"(a3), "r"(b0), "r"(b1));
}

// ---------------------------------------------------------------------------
// Kernel 1 (fused): blocks [0,512) = QKV projection (fp16 mma);
//                   blocks [512,768) = Wo pack (fp16, B-frag layout).
// ---------------------------------------------------------------------------
#define QKV_SMEM_BYTES 41984

__global__ __launch_bounds__(256, 3) void qkv_wo_kernel(
    const float* __restrict__ x,
    const float* __restrict__ Wq, const float* __restrict__ bq,
    const float* __restrict__ Wk, const float* __restrict__ bk,
    const float* __restrict__ Wv, const float* __restrict__ bv,
    const float* __restrict__ Wo)
{
    extern __shared__ __align__(16) uint32_t smq[];
    int tid = threadIdx.x;
    int blk = blockIdx.x;

    if (blk >= 512) {   // ---- Wo pack ----
        float (*t)[65] = (float(*)[65])smq;
        int wid = blk - 512;
        int k0 = (wid & 15)*64, n0 = (wid >> 4)*64;
        for (int idx = tid; idx < 4096; idx += 256) {
            int ki = idx >> 6, n = idx & 63;
            t[ki][n] = Wo[(size_t)(k0 + ki)*EE + n0 + n];
        }
        __syncthreads();
        int nl = tid >> 2, qq = tid & 3;
        uint32_t hv[8];
        #pragma unroll
        for (int j = 0; j < 8; ++j) {
            int pr = 4*j + qq;
            hv[j] = pack_h2(t[2*pr][nl], t[2*pr + 1][nl]);
        }
        size_t ob = (size_t)(n0 + nl)*(EE/2) + (k0 >> 6)*32 + qq*8;
        *(uint4*)&g_wo[ob]     = make_uint4(hv[0], hv[1], hv[2], hv[3]);
        *(uint4*)&g_wo[ob + 4] = make_uint4(hv[4], hv[5], hv[6], hv[7]);
        return;
    }

    // ---- QKV (fp16 mma) ----
    uint32_t* At16 = smq;                     // [128 m][32 pos], XOR-swizzled
    float*    Wsf  = (float*)(smq + 4096);    // [64 k][n] stride 68
    uint32_t* Bs   = smq + 8448;              // [64 n][32 pos], XOR-swizzled
    float*    Vt   = (float*)smq;             // overlay

    int lane = tid & 31, warp = tid >> 5;
    int g = lane >> 2, q = lane & 3;
    int bh = blk & 31, b = bh >> 4, h = bh & 15;
    int s0 = (blk >> 5) * 128, wm = warp * 16;

    for (int idx = tid; idx < 2048; idx += 256) {
        int row = idx >> 4, i = idx & 15;
        float4 v = *(const float4*)&x[((size_t)b*SS + s0 + row)*EE + h*HD + i*4];
        int p0 = ((2*i) & 3)*8 + (i >> 1);
        int p1 = ((2*i + 1) & 3)*8 + (i >> 1);
        int sw0 = ((p0 >> 2) ^ (row & 7))*4 + (p0 & 3);
        int sw1 = ((p1 >> 2) ^ (row & 7))*4 + (p1 & 3);
        At16[row*32 + sw0] = pack_h2(v.x, v.y);
        At16[row*32 + sw1] = pack_h2(v.z, v.w);
    }
    __syncthreads();

    int u0c = ((2*q) ^ g)*4;
    int u1c = ((2*q + 1) ^ g)*4;
    uint32_t qa[8], qg[8];
    {
        int ra0 = (wm + g)*32, ra1 = (wm + g + 8)*32;
        uint4 a0 = *(const uint4*)&At16[ra0 + u0c], a1 = *(const uint4*)&At16[ra0 + u1c];
        uint4 c0 = *(const uint4*)&At16[ra1 + u0c], c1 = *(const uint4*)&At16[ra1 + u1c];
        qa[0]=a0.x; qa[1]=a0.y; qa[2]=a0.z; qa[3]=a0.w; qa[4]=a1.x; qa[5]=a1.y; qa[6]=a1.z; qa[7]=a1.w;
        qg[0]=c0.x; qg[1]=c0.y; qg[2]=c0.z; qg[3]=c0.w; qg[4]=c1.x; qg[5]=c1.y; qg[6]=c1.z; qg[7]=c1.w;
    }

    int r0g = s0 + wm + g, r1g = s0 + wm + g + 8;
    const float* Wp[3] = {Wq, Wk, Wv};
    const float* bp[3] = {bq, bk, bv};

    for (int w = 0; w < 3; ++w) {
        for (int idx = tid; idx < 1024; idx += 256) {
            int row = idx >> 4, c4 = (idx & 15)*4;
            *(float4*)&Wsf[row*68 + c4] = *(const float4*)&Wp[w][(size_t)row*64 + c4];
        }
        __syncthreads();
        {
            int n = tid >> 2, qq = tid & 3;
            #pragma unroll
            for (int j = 0; j < 8; ++j) {
                int c = 8*j + 2*qq;
                int p = qq*8 + j;
                int sw = ((p >> 2) ^ (n & 7))*4 + (p & 3);
                Bs[n*32 + sw] = pack_h2(Wsf[c*68 + n], Wsf[(c + 1)*68 + n]);
            }
        }
        __syncthreads();

        float acc[8][4] = {};
        #pragma unroll
        for (int nb = 0; nb < 8; ++nb) {
            int rb = (8*nb + g)*32;
            uint4 b0 = *(const uint4*)&Bs[rb + u0c];
            uint4 b1 = *(const uint4*)&Bs[rb + u1c];
            mma_f16(acc[nb], qa[0], qg[0], qa[1], qg[1], b0.x, b0.y);
            mma_f16(acc[nb], qa[2], qg[2], qa[3], qg[3], b0.z, b0.w);
            mma_f16(acc[nb], qa[4], qg[4], qa[5], qg[5], b1.x, b1.y);
            mma_f16(acc[nb], qa[6], qg[6], qa[7], qg[7], b1.z, b1.w);
        }

        if (w == 0) {
            #pragma unroll
            for (int nb = 0; nb < 8; ++nb) {
                int c = nb*8 + 2*q;
                float b0 = bp[0][c], b1 = bp[0][c+1];
                g_qb[((size_t)bh*SS + r0g)*32 + q*8 + nb] = pack_h2((acc[nb][0]+b0)*SCALE_L2E, (acc[nb][1]+b1)*SCALE_L2E);
                g_qb[((size_t)bh*SS + r1g)*32 + q*8 + nb] = pack_h2((acc[nb][2]+b0)*SCALE_L2E, (acc[nb][3]+b1)*SCALE_L2E);
            }
            __syncthreads();
        } else if (w == 1) {
            #pragma unroll
            for (int nb = 0; nb < 8; ++nb) {
                int c = nb*8 + 2*q;
                float b0 = bp[1][c], b1 = bp[1][c+1];
                g_kb[((size_t)bh*SS + r0g)*32 + q*8 + nb] = pack_h2(acc[nb][0]+b0, acc[nb][1]+b1);
                g_kb[((size_t)bh*SS + r1g)*32 + q*8 + nb] = pack_h2(acc[nb][2]+b0, acc[nb][3]+b1);
            }
            __syncthreads();
        } else {
            __syncthreads();
            int rl0 = wm + g, rl1 = wm + g + 8;
            #pragma unroll
            for (int nb = 0; nb < 8; ++nb) {
                int c = nb*8 + 2*q;
                float b0 = bp[2][c], b1 = bp[2][c+1];
                Vt[rl0*65 + c] = acc[nb][0]+b0; Vt[rl0*65 + c+1] = acc[nb][1]+b1;
                Vt[rl1*65 + c] = acc[nb][2]+b0; Vt[rl1*65 + c+1] = acc[nb][3]+b1;
            }
            __syncthreads();
            int v = tid & 63, idx2 = tid >> 6, tl = idx2 >> 1, half = idx2 & 1;
            uint32_t hv[16];
            #pragma unroll
            for (int j = 0; j < 16; ++j) {
                int pos = half*16 + j;
                int qv = pos >> 3, kk = (pos & 7) >> 1, hh = pos & 1;
                int sl = tl*64 + 2*(8*kk + 4*hh + qv);
                hv[j] = pack_h2(Vt[sl*65 + v], Vt[(sl+1)*65 + v]);
            }
            size_t ob = ((size_t)bh*64 + v)*(SS/2) + (s0 >> 1) + tl*32 + half*16;
            #pragma unroll
            for (int u = 0; u < 4; ++u)
                *(uint4*)&g_vb[ob + 4*u] = make_uint4(hv[4*u], hv[4*u+1], hv[4*u+2], hv[4*u+3]);
        }
    }
}

// ---------------------------------------------------------------------------
// Kernel 2: attention, fp16 mma, ex2.approx.f16x2 softmax, cp.async 3-stage.
// (exact R15 passing version)
// ---------------------------------------------------------------------------
#define SSTG (2*64*32)                  // 4096 u32 = 16KB
#define ATTN_SMEM_BYTES (3*SSTG*4)      // 49152

__global__ __launch_bounds__(256, 2) void attn_kernel(const float* __restrict__ mask)
{
    extern __shared__ __align__(16) uint32_t smu[];
    uint32_t smb = smem_u32(smu);

    int tid = threadIdx.x, lane = tid & 31, warp = tid >> 5;
    int g = lane >> 2, q = lane & 3;
    int bh = blockIdx.x, b = bh >> 4, h = bh & 15;
    int q0 = blockIdx.y * 128, wr = q0 + warp*16;

    int r8 = tid >> 3, seg = tid & 7;
    const char* srcK = (const char*)g_kb + ((size_t)bh*SS)*128;
    const char* srcV = (const char*)g_vb + ((size_t)bh*64)*(SS/2)*4;

    #pragma unroll
    for (int pf = 0; pf < 2; ++pf) {
        int s0 = pf*64;
        uint32_t base = smb + (pf % 3)*SSTG*4;
        #pragma unroll
        for (int t = 0; t < 2; ++t) {
            int row = r8 + 32*t;
            int sc = (seg ^ (row & 7))*16;
            uint32_t doff = row*128 + seg*16;
            CPA16(base + doff,        srcK + (size_t)(s0+row)*128 + sc);
            CPA16(base + 8192 + doff, srcV + ((size_t)row*(SS/2) + (s0>>1))*4 + sc);
        }
        CPC();
    }

    uint32_t qa[8], qg[8];
    {
        const uint4* p0 = (const uint4*)&g_qb[((size_t)bh*SS + wr + g)*32 + q*8];
        const uint4* p1 = (const uint4*)&g_qb[((size_t)bh*SS + wr + g + 8)*32 + q*8];
        uint4 u0 = p0[0], u1 = p0[1], v0 = p1[0], v1 = p1[1];
        qa[0]=u0.x; qa[1]=u0.y; qa[2]=u0.z; qa[3]=u0.w; qa[4]=u1.x; qa[5]=u1.y; qa[6]=u1.z; qa[7]=u1.w;
        qg[0]=v0.x; qg[1]=v0.y; qg[2]=v0.z; qg[3]=v0.w; qg[4]=v1.x; qg[5]=v1.y; qg[6]=v1.z; qg[7]=v1.w;
    }

    float oacc[8][4] = {};
    float lsum0 = 0.f, lsum1 = 0.f;
    const float* mrow0 = &mask[(size_t)(wr + g)*SS];
    const float* mrow1 = &mask[(size_t)(wr + g + 8)*SS];
    int u0c = ((2*q) ^ g)*4;
    int u1c = ((2*q + 1) ^ g)*4;

    for (int jt = 0; jt < 32; ++jt) {
        if (jt < 31) { CPW(1); } else { CPW(0); }
        __syncthreads();
        if (jt + 2 < 32) {
            int s0n = (jt+2)*64;
            uint32_t base = smb + ((jt+2) % 3)*SSTG*4;
            #pragma unroll
            for (int t = 0; t < 2; ++t) {
                int row = r8 + 32*t;
                int sc = (seg ^ (row & 7))*16;
                uint32_t doff = row*128 + seg*16;
                CPA16(base + doff,        srcK + (size_t)(s0n+row)*128 + sc);
                CPA16(base + 8192 + doff, srcV + ((size_t)row*(SS/2) + (s0n>>1))*4 + sc);
            }
            CPC();
        }

        const uint32_t* Kb = smu + (jt % 3)*SSTG;
        const uint32_t* Vs = Kb + 2048;
        int s0 = jt*64;

        // S = Q K^T
        float sacc[8][4] = {};
        #pragma unroll
        for (int nb = 0; nb < 8; ++nb) {
            int rb = (8*nb + g)*32;
            uint4 k0 = *(const uint4*)&Kb[rb + u0c];
            uint4 k1 = *(const uint4*)&Kb[rb + u1c];
            mma_f16(sacc[nb], qa[0], qg[0], qa[1], qg[1], k0.x, k0.y);
            mma_f16(sacc[nb], qa[2], qg[2], qa[3], qg[3], k0.z, k0.w);
            mma_f16(sacc[nb], qa[4], qg[4], qa[5], qg[5], k1.x, k1.y);
            mma_f16(sacc[nb], qa[6], qg[6], qa[7], qg[7], k1.z, k1.w);
        }

        // P = exp2(S * mask) via ex2.approx.f16x2
        uint32_t ph[8], pg[8];
        float ps0 = 0.f, ps1 = 0.f;
        #pragma unroll
        for (int nb = 0; nb < 8; ++nb) {
            float2 m0 = __ldg((const float2*)&mrow0[s0 + 8*nb + 2*q]);
            float2 m1 = __ldg((const float2*)&mrow1[s0 + 8*nb + 2*q]);
            uint32_t x01 = cvt2_h2(sacc[nb][0]*m0.x, sacc[nb][1]*m0.y);
            uint32_t x23 = cvt2_h2(sacc[nb][2]*m1.x, sacc[nb][3]*m1.y);
            ph[nb] = ex2_h2(x01);
            pg[nb] = ex2_h2(x23);
            float2 f0 = h22f2(ph[nb]);
            float2 f1 = h22f2(pg[nb]);
            ps0 += f0.x + f0.y;
            ps1 += f1.x + f1.y;
        }
        ps0 += __shfl_xor_sync(0xffffffffu, ps0, 1);
        ps0 += __shfl_xor_sync(0xffffffffu, ps0, 2);
        ps1 += __shfl_xor_sync(0xffffffffu, ps1, 1);
        ps1 += __shfl_xor_sync(0xffffffffu, ps1, 2);
        lsum0 += ps0; lsum1 += ps1;

        // O += P V
        #pragma unroll
        for (int nb = 0; nb < 8; ++nb) {
            int rb = (8*nb + g)*32;
            uint4 v0 = *(const uint4*)&Vs[rb + u0c];
            uint4 v1 = *(const uint4*)&Vs[rb + u1c];
            mma_f16(oacc[nb], ph[0], pg[0], ph[1], pg[1], v0.x, v0.y);
            mma_f16(oacc[nb], ph[2], pg[2], ph[3], pg[3], v0.z, v0.w);
            mma_f16(oacc[nb], ph[4], pg[4], ph[5], pg[5], v1.x, v1.y);
            mma_f16(oacc[nb], ph[6], pg[6], ph[7], pg[7], v1.z, v1.w);
        }
    }

    // epilogue: normalize, pack fp16, write in A-fragment layout (pos q*8+nb)
    float inv0 = 1.f/lsum0, inv1 = 1.f/lsum1;
    size_t base0 = ((size_t)b*SS + wr + g)*(EE/2) + h*32;
    size_t base1 = ((size_t)b*SS + wr + g + 8)*(EE/2) + h*32;
    #pragma unroll
    for (int nb = 0; nb < 8; ++nb) {
        int pos = q*8 + nb;
        g_at[base0 + pos] = pack_h2(oacc[nb][0]*inv0, oacc[nb][1]*inv0);
        g_at[base1 + pos] = pack_h2(oacc[nb][2]*inv1, oacc[nb][3]*inv1);
    }
}

// ---------------------------------------------------------------------------
// Kernel 3: output projection, fp16 single-term; A and B via cp.async 3-stage
// (CPW(1), prefetch j+2 — same pipeline shape attention validated).
// Stage layout (u32): A[0,4096) B[4096,6144).  Chunk = 32 u32 = 64 k-values.
// ---------------------------------------------------------------------------
#define OSTG3 6144
#define OUT_SMEM_BYTES (3*OSTG3*4)      // 73728

__global__ __launch_bounds__(256, 2) void out_kernel(
    const float* __restrict__ bo, float* __restrict__ out)
{
    extern __shared__ __align__(16) uint32_t smo[];
    uint32_t smb = smem_u32(smo);

    int tid = threadIdx.x, lane = tid & 31, warp = tid >> 5;
    int g = lane >> 2, q = lane & 3;
    int e0 = blockIdx.x*64, r0 = blockIdx.y*128, wm = warp*16;

    int r8 = tid >> 3, seg = tid & 7;
    const char* srcA = (const char*)g_at + (size_t)r0*(EE/2)*4;
    const char* srcB = (const char*)g_wo + (size_t)e0*(EE/2)*4;

    // prefetch chunks 0 and 1
    #pragma unroll
    for (int pf = 0; pf < 2; ++pf) {
        int kc = pf*32;
        uint32_t base = smb + (pf % 3)*OSTG3*4;
        #pragma unroll
        for (int t = 0; t < 4; ++t) {
            int row = r8 + 32*t;
            int sc = (seg ^ (row & 7))*16;
            CPA16(base + row*128 + seg*16, srcA + ((size_t)row*(EE/2) + kc)*4 + sc);
        }
        #pragma unroll
        for (int t = 0; t < 2; ++t) {
            int row = r8 + 32*t;
            int sc = (seg ^ (row & 7))*16;
            CPA16(base + 16384 + row*128 + seg*16, srcB + ((size_t)row*(EE/2) + kc)*4 + sc);
        }
        CPC();
    }

    int u0c = ((2*q) ^ g)*4;
    int u1c = ((2*q + 1) ^ g)*4;
    int ra0 = (wm + g)*32, ra1 = (wm + g + 8)*32;

    float oacc[8][4] = {};

    for (int j = 0; j < 16; ++j) {
        if (j < 15) { CPW(1); } else { CPW(0); }
        __syncthreads();
        if (j + 2 < 16) {
            int kc = (j + 2)*32;
            uint32_t base = smb + ((j + 2) % 3)*OSTG3*4;
            #pragma unroll
            for (int t = 0; t < 4; ++t) {
                int row = r8 + 32*t;
                int sc = (seg ^ (row & 7))*16;
                CPA16(base + row*128 + seg*16, srcA + ((size_t)row*(EE/2) + kc)*4 + sc);
            }
            #pragma unroll
            for (int t = 0; t < 2; ++t) {
                int row = r8 + 32*t;
                int sc = (seg ^ (row & 7))*16;
                CPA16(base + 16384 + row*128 + seg*16, srcB + ((size_t)row*(EE/2) + kc)*4 + sc);
            }
            CPC();
        }

        const uint32_t* As = smo + (j % 3)*OSTG3;
        const uint32_t* Bs = As + 4096;

        uint4 Aa0 = *(const uint4*)&As[ra0 + u0c], Aa1 = *(const uint4*)&As[ra0 + u1c];
        uint4 Ga0 = *(const uint4*)&As[ra1 + u0c], Ga1 = *(const uint4*)&As[ra1 + u1c];

        #pragma unroll
        for (int nb = 0; nb < 8; ++nb) {
            int rb = (8*nb + g)*32;
            uint4 b0 = *(const uint4*)&Bs[rb + u0c];
            uint4 b1 = *(const uint4*)&Bs[rb + u1c];
            mma_f16(oacc[nb], Aa0.x, Ga0.x, Aa0.y, Ga0.y, b0.x, b0.y);
            mma_f16(oacc[nb], Aa0.z, Ga0.z, Aa0.w, Ga0.w, b0.z, b0.w);
            mma_f16(oacc[nb], Aa1.x, Ga1.x, Aa1.y, Ga1.y, b1.x, b1.y);
            mma_f16(oacc[nb], Aa1.z, Ga1.z, Aa1.w, Ga1.w, b1.z, b1.w);
        }
    }

    float* o0 = &out[(size_t)(r0 + wm + g)*EE + e0];
    float* o1 = &out[(size_t)(r0 + wm + g + 8)*EE + e0];
    #pragma unroll
    for (int nb = 0; nb < 8; ++nb) {
        int c = nb*8 + 2*q;
        float b0 = bo[e0 + c], b1 = bo[e0 + c + 1];
        o0[c] = oacc[nb][0] + b0; o0[c+1] = oacc[nb][1] + b1;
        o1[c] = oacc[nb][2] + b0; o1[c+1] = oacc[nb][3] + b1;
    }
}

// ---------------------------------------------------------------------------
extern "C" void kernel_launch(void* const* d_in, const int* in_sizes, int n_in,
                              void* d_out, int out_size)
{
    const float* x    = (const float*)d_in[0];
    const float* mask = (const float*)d_in[1];
    const float* Wq   = (const float*)d_in[2];
    const float* bq   = (const float*)d_in[3];
    const float* Wk   = (const float*)d_in[4];
    const float* bk   = (const float*)d_in[5];
    const float* Wv   = (const float*)d_in[6];
    const float* bv   = (const float*)d_in[7];
    const float* Wo   = (const float*)d_in[8];
    const float* bo   = (const float*)d_in[9];
    float* out = (float*)d_out;

    cudaFuncSetAttribute(qkv_wo_kernel, cudaFuncAttributeMaxDynamicSharedMemorySize, QKV_SMEM_BYTES);
    cudaFuncSetAttribute(attn_kernel,   cudaFuncAttributeMaxDynamicSharedMemorySize, ATTN_SMEM_BYTES);
    cudaFuncSetAttribute(out_kernel,    cudaFuncAttributeMaxDynamicSharedMemorySize, OUT_SMEM_BYTES);

    qkv_wo_kernel<<<768, 256, QKV_SMEM_BYTES>>>(x, Wq, bq, Wk, bk, Wv, bv, Wo);
    attn_kernel<<<dim3(BH, SS/128), 256, ATTN_SMEM_BYTES>>>(mask);
    out_kernel<<<dim3(EE/64, (BB*SS)/128), 256, OUT_SMEM_BYTES>>>(bo, out);
}